// round 1
// baseline (speedup 1.0000x reference)
#include <cuda_runtime.h>
#include <math.h>

#define B_  512
#define T_  512
#define L_  64
#define H_  512
#define G3_ 1536
#define XW_ (T_ + L_ - 1)   // 575

// Scratch (device globals; no allocations allowed)
__device__ float g_GI1[(size_t)L_ * B_ * G3_];   // [t][b][3H] precomputed input proj (+b_ih1)
__device__ float g_H1[2][(size_t)B_ * H_];       // ping-pong h1
__device__ float g_H2[(size_t)L_ * B_ * H_];     // h2 history [t][b][H]

__device__ __forceinline__ float sigm(float v) { return 1.f / (1.f + __expf(-v)); }

// ---------------------------------------------------------------------------
// Kernel 1: GI1[t,b,j] = sum_k x[b, t+k] * W_ih1[j,k] + b_ih1[j]
// GEMM tile: BM=128 (b), BN=64 (j), BK=16. grid (N/64=24, B/128=4, L=64), 256 thr.
// ---------------------------------------------------------------------------
__global__ __launch_bounds__(256) void k_gi1(const float* __restrict__ x,
                                             const float* __restrict__ W,
                                             const float* __restrict__ bias) {
    __shared__ float As[16][132];   // [k][m], padded
    __shared__ float Bs[16][68];    // [k][n], padded
    const int t  = blockIdx.z;
    const int b0 = blockIdx.y * 128;
    const int j0 = blockIdx.x * 64;
    const int tid = threadIdx.x;
    const int tx = tid & 15, ty = tid >> 4;
    const int lam = tid >> 1, lak = (tid & 1) * 8;   // A loader: row, k-offset
    const int lbn = tid >> 2, lbk = (tid & 3) * 4;   // B loader: row, k-offset

    float acc[8][4];
#pragma unroll
    for (int i = 0; i < 8; i++)
#pragma unroll
        for (int j = 0; j < 4; j++) acc[i][j] = 0.f;

    const float* xa = x + (size_t)(b0 + lam) * XW_ + t + lak;  // unaligned base -> scalar loads
    const float* wa = W + (size_t)(j0 + lbn) * T_ + lbk;       // 16B aligned

    for (int k0 = 0; k0 < T_; k0 += 16) {
        float a_ld[8];
#pragma unroll
        for (int u = 0; u < 8; u++) a_ld[u] = xa[k0 + u];
        float4 wv = *(const float4*)(wa + k0);
        __syncthreads();
#pragma unroll
        for (int u = 0; u < 8; u++) As[lak + u][lam] = a_ld[u];
        Bs[lbk + 0][lbn] = wv.x;
        Bs[lbk + 1][lbn] = wv.y;
        Bs[lbk + 2][lbn] = wv.z;
        Bs[lbk + 3][lbn] = wv.w;
        __syncthreads();
#pragma unroll
        for (int kk = 0; kk < 16; kk++) {
            float4 a0 = *(const float4*)&As[kk][ty * 8];
            float4 a1 = *(const float4*)&As[kk][ty * 8 + 4];
            float4 bv = *(const float4*)&Bs[kk][tx * 4];
            float av[8] = {a0.x, a0.y, a0.z, a0.w, a1.x, a1.y, a1.z, a1.w};
            float bb[4] = {bv.x, bv.y, bv.z, bv.w};
#pragma unroll
            for (int i = 0; i < 8; i++)
#pragma unroll
                for (int j = 0; j < 4; j++) acc[i][j] += av[i] * bb[j];
        }
    }
    const int jc = j0 + tx * 4;
    float4 bv = *(const float4*)(bias + jc);
#pragma unroll
    for (int i = 0; i < 8; i++) {
        int b = b0 + ty * 8 + i;
        float4 o;
        o.x = acc[i][0] + bv.x; o.y = acc[i][1] + bv.y;
        o.z = acc[i][2] + bv.z; o.w = acc[i][3] + bv.w;
        *(float4*)&g_GI1[((size_t)t * B_ + b) * G3_ + jc] = o;
    }
}

// ---------------------------------------------------------------------------
// Kernel 2 (per step): layer-1 GRU cell. gh1 = h1_old @ W_hh1.T (3 gates fused),
// combine with precomputed GI1, write h1_new.
// Tile BM=64 (b), BN=32 (j per gate), BK=16. grid (16, 8), 256 thr.
// ---------------------------------------------------------------------------
__global__ __launch_bounds__(256) void k_step1(int t, const float* __restrict__ h1init,
                                               const float* __restrict__ Whh,
                                               const float* __restrict__ bhh) {
    const float* h1old = (t == 0) ? h1init : g_H1[(t + 1) & 1];
    float* h1new = g_H1[t & 1];
    __shared__ float As[16][68];
    __shared__ float Bg[3][16][36];
    const int b0 = blockIdx.y * 64;
    const int j0 = blockIdx.x * 32;
    const int tid = threadIdx.x;
    const int tx = tid & 15, ty = tid >> 4;
    const int lam = tid >> 2, lak = (tid & 3) * 4;
    const int lbn = tid >> 3, lbk = (tid & 7) * 2;

    float ar[4][2] = {}, az[4][2] = {}, an[4][2] = {};

    const float* Ab = h1old + (size_t)(b0 + lam) * H_ + lak;
    const float* Wr = Whh + (size_t)(j0 + lbn) * H_ + lbk;
    const float* Wz = Wr + (size_t)H_ * H_;
    const float* Wn = Wz + (size_t)H_ * H_;

    for (int k0 = 0; k0 < H_; k0 += 16) {
        float4 av = *(const float4*)(Ab + k0);
        float2 wr = *(const float2*)(Wr + k0);
        float2 wz = *(const float2*)(Wz + k0);
        float2 wn = *(const float2*)(Wn + k0);
        __syncthreads();
        As[lak + 0][lam] = av.x; As[lak + 1][lam] = av.y;
        As[lak + 2][lam] = av.z; As[lak + 3][lam] = av.w;
        Bg[0][lbk][lbn] = wr.x; Bg[0][lbk + 1][lbn] = wr.y;
        Bg[1][lbk][lbn] = wz.x; Bg[1][lbk + 1][lbn] = wz.y;
        Bg[2][lbk][lbn] = wn.x; Bg[2][lbk + 1][lbn] = wn.y;
        __syncthreads();
#pragma unroll
        for (int kk = 0; kk < 16; kk++) {
            float4 a = *(const float4*)&As[kk][ty * 4];
            float2 br = *(const float2*)&Bg[0][kk][tx * 2];
            float2 bz = *(const float2*)&Bg[1][kk][tx * 2];
            float2 bn = *(const float2*)&Bg[2][kk][tx * 2];
            float av2[4] = {a.x, a.y, a.z, a.w};
#pragma unroll
            for (int i = 0; i < 4; i++) {
                ar[i][0] += av2[i] * br.x; ar[i][1] += av2[i] * br.y;
                az[i][0] += av2[i] * bz.x; az[i][1] += av2[i] * bz.y;
                an[i][0] += av2[i] * bn.x; an[i][1] += av2[i] * bn.y;
            }
        }
    }
#pragma unroll
    for (int i = 0; i < 4; i++) {
        int b = b0 + ty * 4 + i;
        const float* gi = &g_GI1[((size_t)t * B_ + b) * G3_];
        const float* ho = h1old + (size_t)b * H_;
        float* hn = h1new + (size_t)b * H_;
#pragma unroll
        for (int jj = 0; jj < 2; jj++) {
            int j = j0 + tx * 2 + jj;
            float r = sigm(gi[j] + ar[i][jj] + bhh[j]);
            float z = sigm(gi[H_ + j] + az[i][jj] + bhh[H_ + j]);
            float n = tanhf(gi[2 * H_ + j] + r * (an[i][jj] + bhh[2 * H_ + j]));
            hn[j] = (1.f - z) * n + z * ho[j];
        }
    }
}

// ---------------------------------------------------------------------------
// Kernel 3 (per step): layer-2 GRU cell. Two fused GEMM phases:
//   phase 0: gi2 = h1_new @ W_ih2.T  -> ar, az, an1
//   phase 1: gh2 = h2_old @ W_hh2.T  -> ar, az, an2  (r/z sum both phases)
// then gates, write h2_new into history.
// ---------------------------------------------------------------------------
__global__ __launch_bounds__(256) void k_step2(int t, const float* __restrict__ h2init,
                                               const float* __restrict__ Wih,
                                               const float* __restrict__ Whh,
                                               const float* __restrict__ bih,
                                               const float* __restrict__ bhh) {
    const float* h1 = g_H1[t & 1];
    const float* h2old = (t == 0) ? h2init : (g_H2 + (size_t)(t - 1) * B_ * H_);
    float* h2new = g_H2 + (size_t)t * B_ * H_;
    __shared__ float As[16][68];
    __shared__ float Bg[3][16][36];
    const int b0 = blockIdx.y * 64;
    const int j0 = blockIdx.x * 32;
    const int tid = threadIdx.x;
    const int tx = tid & 15, ty = tid >> 4;
    const int lam = tid >> 2, lak = (tid & 3) * 4;
    const int lbn = tid >> 3, lbk = (tid & 7) * 2;

    float ar[4][2] = {}, az[4][2] = {}, an1[4][2] = {}, an2[4][2] = {};

    auto phase = [&](const float* Aptr, const float* Wptr, float (&an)[4][2]) {
        const float* Ab = Aptr + (size_t)(b0 + lam) * H_ + lak;
        const float* Wr = Wptr + (size_t)(j0 + lbn) * H_ + lbk;
        const float* Wz = Wr + (size_t)H_ * H_;
        const float* Wn = Wz + (size_t)H_ * H_;
        for (int k0 = 0; k0 < H_; k0 += 16) {
            float4 av = *(const float4*)(Ab + k0);
            float2 wr = *(const float2*)(Wr + k0);
            float2 wz = *(const float2*)(Wz + k0);
            float2 wn = *(const float2*)(Wn + k0);
            __syncthreads();
            As[lak + 0][lam] = av.x; As[lak + 1][lam] = av.y;
            As[lak + 2][lam] = av.z; As[lak + 3][lam] = av.w;
            Bg[0][lbk][lbn] = wr.x; Bg[0][lbk + 1][lbn] = wr.y;
            Bg[1][lbk][lbn] = wz.x; Bg[1][lbk + 1][lbn] = wz.y;
            Bg[2][lbk][lbn] = wn.x; Bg[2][lbk + 1][lbn] = wn.y;
            __syncthreads();
#pragma unroll
            for (int kk = 0; kk < 16; kk++) {
                float4 a = *(const float4*)&As[kk][ty * 4];
                float2 br = *(const float2*)&Bg[0][kk][tx * 2];
                float2 bz = *(const float2*)&Bg[1][kk][tx * 2];
                float2 bn = *(const float2*)&Bg[2][kk][tx * 2];
                float av2[4] = {a.x, a.y, a.z, a.w};
#pragma unroll
                for (int i = 0; i < 4; i++) {
                    ar[i][0] += av2[i] * br.x; ar[i][1] += av2[i] * br.y;
                    az[i][0] += av2[i] * bz.x; az[i][1] += av2[i] * bz.y;
                    an[i][0] += av2[i] * bn.x; an[i][1] += av2[i] * bn.y;
                }
            }
        }
    };
    phase(h1, Wih, an1);
    phase(h2old, Whh, an2);

#pragma unroll
    for (int i = 0; i < 4; i++) {
        int b = b0 + ty * 4 + i;
        const float* ho = h2old + (size_t)b * H_;
        float* hn = h2new + (size_t)b * H_;
#pragma unroll
        for (int jj = 0; jj < 2; jj++) {
            int j = j0 + tx * 2 + jj;
            float r = sigm(ar[i][jj] + bih[j] + bhh[j]);
            float z = sigm(az[i][jj] + bih[H_ + j] + bhh[H_ + j]);
            float n = tanhf(an1[i][jj] + bih[2 * H_ + j] + r * (an2[i][jj] + bhh[2 * H_ + j]));
            hn[j] = (1.f - z) * n + z * ho[j];
        }
    }
}

// ---------------------------------------------------------------------------
// Kernel 4: ys[b, t] = dot(g_H2[t][b], W_fc) + b_fc. One warp per (b, t).
// ---------------------------------------------------------------------------
__global__ __launch_bounds__(256) void k_fc(const float* __restrict__ Wfc,
                                            const float* __restrict__ bfc,
                                            float* __restrict__ out) {
    int w = (blockIdx.x * 256 + threadIdx.x) >> 5;   // 0..32767
    int lane = threadIdx.x & 31;
    int b = w >> 6, tt = w & 63;
    const float* h = g_H2 + ((size_t)tt * B_ + b) * H_;
    float s = 0.f;
#pragma unroll
    for (int q = 0; q < H_ / 32; q++) {
        int k = lane + 32 * q;
        s += h[k] * Wfc[k];
    }
#pragma unroll
    for (int off = 16; off; off >>= 1) s += __shfl_down_sync(0xffffffffu, s, off);
    if (lane == 0) out[(size_t)b * L_ + tt] = s + bfc[0];
}

// ---------------------------------------------------------------------------
// Kernel 5: emit final hidden states: out[B*L ..] = h1_final, then h2_final.
// ---------------------------------------------------------------------------
__global__ __launch_bounds__(256) void k_copy(float* __restrict__ out) {
    int i = blockIdx.x * 256 + threadIdx.x;
    const int n = B_ * H_;
    if (i < n) {
        out[B_ * L_ + i] = g_H1[(L_ - 1) & 1][i];                 // h1 after step 63
        out[B_ * L_ + n + i] = g_H2[(size_t)(L_ - 1) * n + i];    // h2 after step 63
    }
}

extern "C" void kernel_launch(void* const* d_in, const int* in_sizes, int n_in,
                              void* d_out, int out_size) {
    const float* x    = (const float*)d_in[0];
    const float* h1i  = (const float*)d_in[1];
    const float* h2i  = (const float*)d_in[2];
    const float* Wih1 = (const float*)d_in[3];
    const float* Whh1 = (const float*)d_in[4];
    const float* bih1 = (const float*)d_in[5];
    const float* bhh1 = (const float*)d_in[6];
    const float* Wih2 = (const float*)d_in[7];
    const float* Whh2 = (const float*)d_in[8];
    const float* bih2 = (const float*)d_in[9];
    const float* bhh2 = (const float*)d_in[10];
    const float* Wfc  = (const float*)d_in[11];
    const float* bfc  = (const float*)d_in[12];
    float* out = (float*)d_out;

    // Precompute all 64 input projections in one big GEMM
    k_gi1<<<dim3(24, 4, 64), 256>>>(x, Wih1, bih1);

    // Sequential recurrence: 2 fused GEMM+gate kernels per step
    for (int t = 0; t < L_; t++) {
        k_step1<<<dim3(16, 8), 256>>>(t, h1i, Whh1, bhh1);
        k_step2<<<dim3(16, 8), 256>>>(t, h2i, Wih2, Whh2, bih2, bhh2);
    }

    // Output head over the full h2 history + final hidden states
    k_fc<<<4096, 256>>>(Wfc, bfc, out);
    k_copy<<<(B_ * H_ + 255) / 256, 256>>>(out);
}